// round 6
// baseline (speedup 1.0000x reference)
#include <cuda_runtime.h>
#include <cuda_bf16.h>
#include <cuda_fp16.h>
#include <cstdint>

#define NNODES 100000
#define EEDGES 1600000
#define HDIM   128

#define SCAN_BLK 1024
#define SCAN_T   256
#define NSCAN    ((NNODES + SCAN_BLK - 1) / SCAN_BLK)   // 98

#define MTILE   128
#define NTILES  ((NNODES + MTILE - 1) / MTILE)          // 782
#define PADH    136                                      // halves per padded row (272 B)
#define TILEB   (128 * PADH * 2)                         // 34816 B per bf16 tile
#define SMEM_DYN (4 * TILEB)                             // A_hi, A_lo, W_hi, W_lo

// ---------------------------------------------------------------------------
// Scratch (device globals)
// ---------------------------------------------------------------------------
__device__ __half g_h16a[(size_t)NNODES * HDIM];  // 25.6 MB ping
__device__ __half g_h16b[(size_t)NNODES * HDIM];  // 25.6 MB pong
__device__ float  g_dinv[NNODES];
__device__ int    g_deg[NNODES];
__device__ int    g_off[NNODES + 1];
__device__ int    g_cur[NNODES];
__device__ int    g_csr[EEDGES];
__device__ int    g_bsum[NSCAN];
__device__ int    g_bbase[NSCAN];
__device__ __nv_bfloat16 g_Wt[3][2][128 * 128];   // k-major W, hi/lo split

// ---------------------------------------------------------------------------
__device__ __forceinline__ uint32_t smem_u32(const void* p) {
    uint32_t a;
    asm("{ .reg .u64 t; cvta.to.shared.u64 t, %1; cvt.u32.u64 %0, t; }"
        : "=r"(a) : "l"(p));
    return a;
}

#define LDSM_X4(r, a) \
    asm volatile("ldmatrix.sync.aligned.m8n8.x4.shared.b16 {%0,%1,%2,%3}, [%4];" \
                 : "=r"((r)[0]), "=r"((r)[1]), "=r"((r)[2]), "=r"((r)[3]) : "r"(a))
#define LDSM_X4T(r, a) \
    asm volatile("ldmatrix.sync.aligned.m8n8.x4.trans.shared.b16 {%0,%1,%2,%3}, [%4];" \
                 : "=r"((r)[0]), "=r"((r)[1]), "=r"((r)[2]), "=r"((r)[3]) : "r"(a))
#define MMA_BF16(c, a, b0, b1) \
    asm volatile("mma.sync.aligned.m16n8k16.row.col.f32.bf16.bf16.f32 " \
                 "{%0,%1,%2,%3}, {%4,%5,%6,%7}, {%8,%9}, {%0,%1,%2,%3};" \
                 : "+f"((c)[0]), "+f"((c)[1]), "+f"((c)[2]), "+f"((c)[3]) \
                 : "r"((a)[0]), "r"((a)[1]), "r"((a)[2]), "r"((a)[3]), \
                   "r"(b0), "r"(b1))

// ---------------------------------------------------------------------------
// Degree / CSR build
// ---------------------------------------------------------------------------
__global__ void zero_deg() {
    int i = blockIdx.x * blockDim.x + threadIdx.x;
    if (i < NNODES) g_deg[i] = 0;
}
__global__ void deg_count(const int* __restrict__ dst) {
    int e = blockIdx.x * blockDim.x + threadIdx.x;
    if (e < EEDGES) atomicAdd(&g_deg[dst[e]], 1);
}
__global__ void dinv_kernel() {
    int i = blockIdx.x * blockDim.x + threadIdx.x;
    if (i < NNODES) g_dinv[i] = rsqrtf((float)g_deg[i] + 1.0f);
}
__global__ __launch_bounds__(SCAN_T)
void scan1() {
    __shared__ int sh[SCAN_T];
    int b = blockIdx.x, t = threadIdx.x;
    int base = b * SCAN_BLK + t * 4;
    int v[4];
#pragma unroll
    for (int j = 0; j < 4; j++) {
        int i = base + j;
        v[j] = (i < NNODES) ? g_deg[i] : 0;
    }
    int tot = v[0] + v[1] + v[2] + v[3];
    sh[t] = tot;
    __syncthreads();
    for (int o = 1; o < SCAN_T; o <<= 1) {
        int x = 0;
        if (t >= o) x = sh[t - o];
        __syncthreads();
        if (t >= o) sh[t] += x;
        __syncthreads();
    }
    int run = sh[t] - tot;
#pragma unroll
    for (int j = 0; j < 4; j++) {
        int i = base + j;
        if (i < NNODES) g_off[i] = run;
        run += v[j];
    }
    if (t == SCAN_T - 1) g_bsum[b] = sh[t];
}
__global__ void scan2() {
    if (threadIdx.x == 0 && blockIdx.x == 0) {
        int run = 0;
        for (int i = 0; i < NSCAN; i++) { g_bbase[i] = run; run += g_bsum[i]; }
        g_off[NNODES] = run;
    }
}
__global__ void scan3() {
    int i = blockIdx.x * blockDim.x + threadIdx.x;
    if (i < NNODES) {
        int v = g_off[i] + g_bbase[i / SCAN_BLK];
        g_off[i] = v;
        g_cur[i] = v;
    }
}
__global__ void csr_fill(const int* __restrict__ src, const int* __restrict__ dst) {
    int e = blockIdx.x * blockDim.x + threadIdx.x;
    if (e < EEDGES) {
        int d = dst[e];
        int slot = atomicAdd(&g_cur[d], 1);
        g_csr[slot] = src[e];
    }
}

// ---------------------------------------------------------------------------
// Prep: split W (k-major, [k][n]) into bf16 hi/lo.
// ---------------------------------------------------------------------------
__global__ void prep_w(const float* __restrict__ W0, const float* __restrict__ W1,
                       const float* __restrict__ W2) {
    int idx = blockIdx.x * blockDim.x + threadIdx.x;
    if (idx >= 3 * 16384) return;
    int l = idx >> 14;
    int e = idx & 16383;
    const float* W = (l == 0) ? W0 : (l == 1) ? W1 : W2;
    float v = W[e];
    __nv_bfloat16 hi = __float2bfloat16(v);
    __nv_bfloat16 lo = __float2bfloat16(v - __bfloat162float(hi));
    g_Wt[l][0][e] = hi;
    g_Wt[l][1][e] = lo;
}

// ---------------------------------------------------------------------------
// Shared device helpers for the GEMM kernels
// ---------------------------------------------------------------------------
__device__ __forceinline__ void fill_w_tiles(char* sm, int wl, int tid) {
    const uint4* whi = (const uint4*)g_Wt[wl][0];
    const uint4* wlo = (const uint4*)g_Wt[wl][1];
#pragma unroll
    for (int i = tid; i < 2048; i += 512) {
        int r  = i >> 4;
        int c4 = i & 15;
        uint32_t off = (uint32_t)r * (PADH * 2) + c4 * 16;
        *(uint4*)(sm + 2 * TILEB + off) = __ldg(&whi[i]);
        *(uint4*)(sm + 3 * TILEB + off) = __ldg(&wlo[i]);
    }
}

__device__ __forceinline__ void store_a_split(char* sm, int r, int c4, float4 v) {
    __nv_bfloat16 h0 = __float2bfloat16(v.x), h1 = __float2bfloat16(v.y);
    __nv_bfloat16 h2 = __float2bfloat16(v.z), h3 = __float2bfloat16(v.w);
    __nv_bfloat16 l0 = __float2bfloat16(v.x - __bfloat162float(h0));
    __nv_bfloat16 l1 = __float2bfloat16(v.y - __bfloat162float(h1));
    __nv_bfloat16 l2 = __float2bfloat16(v.z - __bfloat162float(h2));
    __nv_bfloat16 l3 = __float2bfloat16(v.w - __bfloat162float(h3));
    uint32_t off = (uint32_t)r * (PADH * 2) + c4 * 8;
    *(__nv_bfloat162*)(sm + off)             = __halves2bfloat162(h0, h1);
    *(__nv_bfloat162*)(sm + off + 4)         = __halves2bfloat162(h2, h3);
    *(__nv_bfloat162*)(sm + TILEB + off)     = __halves2bfloat162(l0, l1);
    *(__nv_bfloat162*)(sm + TILEB + off + 4) = __halves2bfloat162(l2, l3);
}

// MMA main loop + fp16 epilogue (shared by both GEMM kernels)
__device__ __forceinline__ void mma_and_store(const char* sm_c, uint32_t uBase,
                                              int wid, int lane, int bm,
                                              const float* dinv,
                                              __half* __restrict__ C16) {
    const uint32_t uAhi = uBase;
    const uint32_t uAlo = uBase + TILEB;
    const uint32_t uWhi = uBase + 2 * TILEB;
    const uint32_t uWlo = uBase + 3 * TILEB;
    const int mt = wid >> 1;
    const int nh = wid & 1;
    const int lr = lane & 15;
    const int lc = lane >> 4;

    float acc[8][4];
#pragma unroll
    for (int j = 0; j < 8; j++)
#pragma unroll
        for (int q = 0; q < 4; q++) acc[j][q] = 0.0f;

#pragma unroll
    for (int ks = 0; ks < 8; ks++) {
        uint32_t aoff = (uint32_t)(mt * 16 + lr) * (PADH * 2) + (ks * 16 + lc * 8) * 2;
        uint32_t aH[4], aL[4];
        LDSM_X4(aH, uAhi + aoff);
        LDSM_X4(aL, uAlo + aoff);

        uint32_t brow = (uint32_t)(ks * 16 + lr) * (PADH * 2);
        uint32_t bH[4][4], bL[4][4];
#pragma unroll
        for (int p = 0; p < 4; p++) {
            uint32_t boff = brow + (nh * 64 + p * 16 + lc * 8) * 2;
            LDSM_X4T(bH[p], uWhi + boff);
            LDSM_X4T(bL[p], uWlo + boff);
        }
#pragma unroll
        for (int p = 0; p < 4; p++) {
            MMA_BF16(acc[2 * p],     aH, bH[p][0], bH[p][1]);
            MMA_BF16(acc[2 * p + 1], aH, bH[p][2], bH[p][3]);
            MMA_BF16(acc[2 * p],     aL, bH[p][0], bH[p][1]);
            MMA_BF16(acc[2 * p + 1], aL, bH[p][2], bH[p][3]);
            MMA_BF16(acc[2 * p],     aH, bL[p][0], bL[p][1]);
            MMA_BF16(acc[2 * p + 1], aH, bL[p][2], bL[p][3]);
        }
    }

    int row0 = bm + mt * 16 + (lane >> 2);
    int row1 = row0 + 8;
    float s0 = (row0 < NNODES) ? __ldg(&dinv[row0]) : 0.f;
    float s1 = (row1 < NNODES) ? __ldg(&dinv[row1]) : 0.f;
    int colb = nh * 64 + (lane & 3) * 2;
    if (row0 < NNODES) {
        __half* o = &C16[(size_t)row0 * 128 + colb];
#pragma unroll
        for (int j = 0; j < 8; j++)
            *(__half2*)(o + j * 8) = __floats2half2_rn(acc[j][0] * s0, acc[j][1] * s0);
    }
    if (row1 < NNODES) {
        __half* o = &C16[(size_t)row1 * 128 + colb];
#pragma unroll
        for (int j = 0; j < 8; j++)
            *(__half2*)(o + j * 8) = __floats2half2_rn(acc[j][2] * s1, acc[j][3] * s1);
    }
}

// ---------------------------------------------------------------------------
// Layer-0 GEMM: h16[row,:] = fp16( dinv[row] * ( x @ W0 ) )
// ---------------------------------------------------------------------------
__global__ __launch_bounds__(512, 1)
void gemm_mma(const float* __restrict__ A, int wl,
              const float* __restrict__ dinv, __half* __restrict__ C16) {
    extern __shared__ char sm[];
    const int tid  = threadIdx.x;
    const int wid  = tid >> 5;
    const int lane = tid & 31;
    const int bm   = blockIdx.x * MTILE;
    const uint32_t uBase = smem_u32(sm);

    fill_w_tiles(sm, wl, tid);

#pragma unroll
    for (int idx = tid; idx < MTILE * 32; idx += 512) {
        int r  = idx >> 5;
        int c4 = idx & 31;
        int row = bm + r;
        float4 v = make_float4(0.f, 0.f, 0.f, 0.f);
        if (row < NNODES)
            v = *(const float4*)&A[(size_t)row * 128 + c4 * 4];
        store_a_split(sm, r, c4, v);
    }
    __syncthreads();

    mma_and_store(sm, uBase, wid, lane, bm, dinv, C16);
}

// ---------------------------------------------------------------------------
// Fused layers 1..2: per CTA, gather its 128 A-rows from h16 (CSR), apply
// dinv/bias/relu, split bf16, then GEMM with W[wl] and store fp16 out.
// Warp w gathers rows {w, w+16, ..., w+112}; lane owns cols [lane*4, lane*4+4).
// ---------------------------------------------------------------------------
__global__ __launch_bounds__(512, 1)
void fused_gg(const __half* __restrict__ hs, int wl,
              const float* __restrict__ bias, const float* __restrict__ dinv,
              __half* __restrict__ C16) {
    extern __shared__ char sm[];
    const int tid  = threadIdx.x;
    const int wid  = tid >> 5;
    const int lane = tid & 31;
    const int bm   = blockIdx.x * MTILE;
    const uint32_t uBase = smem_u32(sm);

    fill_w_tiles(sm, wl, tid);

    const uint2* hp = (const uint2*)hs;
    float4 bb = *(const float4*)&bias[lane * 4];

#pragma unroll
    for (int rr = 0; rr < 8; rr++) {
        int r = wid + rr * 16;
        int d = bm + r;
        float4 acc = make_float4(0.f, 0.f, 0.f, 0.f);
        if (d < NNODES) {
            uint2 u = __ldg(&hp[d * 32 + lane]);
            float2 a = __half22float2(*(const __half2*)&u.x);
            float2 b = __half22float2(*(const __half2*)&u.y);
            acc = make_float4(a.x, a.y, b.x, b.y);

            int e    = __ldg(&g_off[d]);
            int eend = __ldg(&g_off[d + 1]);
            // 8-deep unroll for MLP
            for (; e + 8 <= eend; e += 8) {
                uint2 u0 = __ldg(&hp[__ldg(&g_csr[e + 0]) * 32 + lane]);
                uint2 u1 = __ldg(&hp[__ldg(&g_csr[e + 1]) * 32 + lane]);
                uint2 u2 = __ldg(&hp[__ldg(&g_csr[e + 2]) * 32 + lane]);
                uint2 u3 = __ldg(&hp[__ldg(&g_csr[e + 3]) * 32 + lane]);
                uint2 u4 = __ldg(&hp[__ldg(&g_csr[e + 4]) * 32 + lane]);
                uint2 u5 = __ldg(&hp[__ldg(&g_csr[e + 5]) * 32 + lane]);
                uint2 u6 = __ldg(&hp[__ldg(&g_csr[e + 6]) * 32 + lane]);
                uint2 u7 = __ldg(&hp[__ldg(&g_csr[e + 7]) * 32 + lane]);
#define ACC_U(u) { \
                float2 _a = __half22float2(*(const __half2*)&(u).x); \
                float2 _b = __half22float2(*(const __half2*)&(u).y); \
                acc.x += _a.x; acc.y += _a.y; acc.z += _b.x; acc.w += _b.y; }
                ACC_U(u0) ACC_U(u1) ACC_U(u2) ACC_U(u3)
                ACC_U(u4) ACC_U(u5) ACC_U(u6) ACC_U(u7)
            }
            for (; e < eend; e++) {
                uint2 u2x = __ldg(&hp[__ldg(&g_csr[e]) * 32 + lane]);
                ACC_U(u2x)
#undef ACC_U
            }
            float sc = __ldg(&g_dinv[d]);
            acc.x = fmaxf(acc.x * sc + bb.x, 0.f);
            acc.y = fmaxf(acc.y * sc + bb.y, 0.f);
            acc.z = fmaxf(acc.z * sc + bb.z, 0.f);
            acc.w = fmaxf(acc.w * sc + bb.w, 0.f);
        }
        store_a_split(sm, r, lane, acc);
    }
    __syncthreads();

    mma_and_store(sm, uBase, wid, lane, bm, dinv, C16);
}

// ---------------------------------------------------------------------------
// Final gather: out = relu( dinv[d]*(h16[d] + sum h16[src]) + b2 ), fp32 out.
// ---------------------------------------------------------------------------
__global__ __launch_bounds__(256)
void gather_final(const __half* __restrict__ hs, const float* __restrict__ bias,
                  float* __restrict__ out) {
    int w = (int)((blockIdx.x * (unsigned)blockDim.x + threadIdx.x) >> 5);
    if (w >= NNODES) return;
    int lane = threadIdx.x & 31;
    const uint2* hp = (const uint2*)hs;

    int e    = g_off[w];
    int eend = g_off[w + 1];

    float4 acc;
    {
        uint2 u = __ldg(&hp[w * 32 + lane]);
        float2 a = __half22float2(*(const __half2*)&u.x);
        float2 b = __half22float2(*(const __half2*)&u.y);
        acc = make_float4(a.x, a.y, b.x, b.y);
    }

#define ACC_U(u) { \
    float2 _a = __half22float2(*(const __half2*)&(u).x); \
    float2 _b = __half22float2(*(const __half2*)&(u).y); \
    acc.x += _a.x; acc.y += _a.y; acc.z += _b.x; acc.w += _b.y; }
    for (; e + 8 <= eend; e += 8) {
        uint2 u0 = __ldg(&hp[__ldg(&g_csr[e + 0]) * 32 + lane]);
        uint2 u1 = __ldg(&hp[__ldg(&g_csr[e + 1]) * 32 + lane]);
        uint2 u2 = __ldg(&hp[__ldg(&g_csr[e + 2]) * 32 + lane]);
        uint2 u3 = __ldg(&hp[__ldg(&g_csr[e + 3]) * 32 + lane]);
        uint2 u4 = __ldg(&hp[__ldg(&g_csr[e + 4]) * 32 + lane]);
        uint2 u5 = __ldg(&hp[__ldg(&g_csr[e + 5]) * 32 + lane]);
        uint2 u6 = __ldg(&hp[__ldg(&g_csr[e + 6]) * 32 + lane]);
        uint2 u7 = __ldg(&hp[__ldg(&g_csr[e + 7]) * 32 + lane]);
        ACC_U(u0) ACC_U(u1) ACC_U(u2) ACC_U(u3)
        ACC_U(u4) ACC_U(u5) ACC_U(u6) ACC_U(u7)
    }
    for (; e < eend; e++) {
        uint2 u = __ldg(&hp[__ldg(&g_csr[e]) * 32 + lane]);
        ACC_U(u)
    }
#undef ACC_U

    float sc = __ldg(&g_dinv[w]);
    float4 bb = *(const float4*)&bias[lane * 4];
    acc.x = fmaxf(acc.x * sc + bb.x, 0.f);
    acc.y = fmaxf(acc.y * sc + bb.y, 0.f);
    acc.z = fmaxf(acc.z * sc + bb.z, 0.f);
    acc.w = fmaxf(acc.w * sc + bb.w, 0.f);
    ((float4*)out)[w * 32 + lane] = acc;
}

// ---------------------------------------------------------------------------
extern "C" void kernel_launch(void* const* d_in, const int* in_sizes, int n_in,
                              void* d_out, int out_size) {
    const float* x  = (const float*)d_in[0];
    const int*   ei = (const int*)d_in[1];
    const float* W0 = (const float*)d_in[2];
    const float* b0 = (const float*)d_in[3];
    const float* W1 = (const float*)d_in[4];
    const float* b1 = (const float*)d_in[5];
    const float* W2 = (const float*)d_in[6];
    const float* b2 = (const float*)d_in[7];
    const int* src = ei;
    const int* dst = ei + EEDGES;

    __half *h16a, *h16b;
    float* dinv;
    cudaGetSymbolAddress((void**)&h16a, g_h16a);
    cudaGetSymbolAddress((void**)&h16b, g_h16b);
    cudaGetSymbolAddress((void**)&dinv, g_dinv);

    cudaFuncSetAttribute(gemm_mma, cudaFuncAttributeMaxDynamicSharedMemorySize, SMEM_DYN);
    cudaFuncSetAttribute(fused_gg, cudaFuncAttributeMaxDynamicSharedMemorySize, SMEM_DYN);

    // Degree + CSR build
    zero_deg<<<(NNODES + 255) / 256, 256>>>();
    deg_count<<<(EEDGES + 255) / 256, 256>>>(dst);
    dinv_kernel<<<(NNODES + 255) / 256, 256>>>();
    scan1<<<NSCAN, SCAN_T>>>();
    scan2<<<1, 32>>>();
    scan3<<<(NNODES + 255) / 256, 256>>>();
    csr_fill<<<(EEDGES + 255) / 256, 256>>>(src, dst);
    prep_w<<<(3 * 16384 + 255) / 256, 256>>>(W0, W1, W2);

    const int gather_blocks = (NNODES + 7) / 8;

    gemm_mma<<<NTILES, 512, SMEM_DYN>>>(x, 0, dinv, h16a);
    fused_gg<<<NTILES, 512, SMEM_DYN>>>(h16a, 1, b0, dinv, h16b);
    fused_gg<<<NTILES, 512, SMEM_DYN>>>(h16b, 2, b1, dinv, h16a);
    gather_final<<<gather_blocks, 256>>>(h16a, b2, (float*)d_out);
}

// round 7
// speedup vs baseline: 1.7731x; 1.7731x over previous
#include <cuda_runtime.h>
#include <cuda_bf16.h>
#include <cuda_fp16.h>
#include <cstdint>

#define NNODES 100000
#define EEDGES 1600000
#define HDIM   128

#define SCAN_BLK 1024
#define SCAN_T   256
#define NSCAN    ((NNODES + SCAN_BLK - 1) / SCAN_BLK)   // 98

#define MTILE   128
#define NTILES  ((NNODES + MTILE - 1) / MTILE)          // 782
#define PADH    136                                      // halves per padded row (272 B)
#define TILEB   (128 * PADH * 2)                         // 34816 B per bf16 tile
#define SMEM_DYN (4 * TILEB)                             // A_hi, A_lo, W_hi, W_lo

// ---------------------------------------------------------------------------
// Scratch (device globals)
// ---------------------------------------------------------------------------
__device__ __half g_h16a[(size_t)NNODES * HDIM];  // 25.6 MB ping
__device__ __half g_h16b[(size_t)NNODES * HDIM];  // 25.6 MB pong
__device__ float  g_dinv[NNODES];
__device__ int    g_deg[NNODES];
__device__ int    g_off[NNODES + 1];
__device__ int    g_cur[NNODES];
__device__ int    g_csr[EEDGES];
__device__ int    g_bsum[NSCAN];
__device__ int    g_bbase[NSCAN];
__device__ __nv_bfloat16 g_Wt[3][2][128 * 128];   // k-major W, hi/lo split

// ---------------------------------------------------------------------------
__device__ __forceinline__ uint32_t smem_u32(const void* p) {
    uint32_t a;
    asm("{ .reg .u64 t; cvta.to.shared.u64 t, %1; cvt.u32.u64 %0, t; }"
        : "=r"(a) : "l"(p));
    return a;
}

#define LDSM_X4(r, a) \
    asm volatile("ldmatrix.sync.aligned.m8n8.x4.shared.b16 {%0,%1,%2,%3}, [%4];" \
                 : "=r"((r)[0]), "=r"((r)[1]), "=r"((r)[2]), "=r"((r)[3]) : "r"(a))
#define LDSM_X4T(r, a) \
    asm volatile("ldmatrix.sync.aligned.m8n8.x4.trans.shared.b16 {%0,%1,%2,%3}, [%4];" \
                 : "=r"((r)[0]), "=r"((r)[1]), "=r"((r)[2]), "=r"((r)[3]) : "r"(a))
#define MMA_BF16(c, a, b0, b1) \
    asm volatile("mma.sync.aligned.m16n8k16.row.col.f32.bf16.bf16.f32 " \
                 "{%0,%1,%2,%3}, {%4,%5,%6,%7}, {%8,%9}, {%0,%1,%2,%3};" \
                 : "+f"((c)[0]), "+f"((c)[1]), "+f"((c)[2]), "+f"((c)[3]) \
                 : "r"((a)[0]), "r"((a)[1]), "r"((a)[2]), "r"((a)[3]), \
                   "r"(b0), "r"(b1))

// ---------------------------------------------------------------------------
// Degree / CSR build
// ---------------------------------------------------------------------------
__global__ void zero_deg() {
    int i = blockIdx.x * blockDim.x + threadIdx.x;
    if (i < NNODES) g_deg[i] = 0;
}
__global__ void deg_count(const int* __restrict__ dst) {
    int e = blockIdx.x * blockDim.x + threadIdx.x;
    if (e < EEDGES) atomicAdd(&g_deg[dst[e]], 1);
}
__global__ void dinv_kernel() {
    int i = blockIdx.x * blockDim.x + threadIdx.x;
    if (i < NNODES) g_dinv[i] = rsqrtf((float)g_deg[i] + 1.0f);
}
__global__ __launch_bounds__(SCAN_T)
void scan1() {
    __shared__ int sh[SCAN_T];
    int b = blockIdx.x, t = threadIdx.x;
    int base = b * SCAN_BLK + t * 4;
    int v[4];
#pragma unroll
    for (int j = 0; j < 4; j++) {
        int i = base + j;
        v[j] = (i < NNODES) ? g_deg[i] : 0;
    }
    int tot = v[0] + v[1] + v[2] + v[3];
    sh[t] = tot;
    __syncthreads();
    for (int o = 1; o < SCAN_T; o <<= 1) {
        int x = 0;
        if (t >= o) x = sh[t - o];
        __syncthreads();
        if (t >= o) sh[t] += x;
        __syncthreads();
    }
    int run = sh[t] - tot;
#pragma unroll
    for (int j = 0; j < 4; j++) {
        int i = base + j;
        if (i < NNODES) g_off[i] = run;
        run += v[j];
    }
    if (t == SCAN_T - 1) g_bsum[b] = sh[t];
}
__global__ void scan2() {
    if (threadIdx.x == 0 && blockIdx.x == 0) {
        int run = 0;
        for (int i = 0; i < NSCAN; i++) { g_bbase[i] = run; run += g_bsum[i]; }
        g_off[NNODES] = run;
    }
}
__global__ void scan3() {
    int i = blockIdx.x * blockDim.x + threadIdx.x;
    if (i < NNODES) {
        int v = g_off[i] + g_bbase[i / SCAN_BLK];
        g_off[i] = v;
        g_cur[i] = v;
    }
}
__global__ void csr_fill(const int* __restrict__ src, const int* __restrict__ dst) {
    int e = blockIdx.x * blockDim.x + threadIdx.x;
    if (e < EEDGES) {
        int d = dst[e];
        int slot = atomicAdd(&g_cur[d], 1);
        g_csr[slot] = src[e];
    }
}

// ---------------------------------------------------------------------------
// Prep: split W (k-major, [k][n]) into bf16 hi/lo.
// ---------------------------------------------------------------------------
__global__ void prep_w(const float* __restrict__ W0, const float* __restrict__ W1,
                       const float* __restrict__ W2) {
    int idx = blockIdx.x * blockDim.x + threadIdx.x;
    if (idx >= 3 * 16384) return;
    int l = idx >> 14;
    int e = idx & 16383;
    const float* W = (l == 0) ? W0 : (l == 1) ? W1 : W2;
    float v = W[e];
    __nv_bfloat16 hi = __float2bfloat16(v);
    __nv_bfloat16 lo = __float2bfloat16(v - __bfloat162float(hi));
    g_Wt[l][0][e] = hi;
    g_Wt[l][1][e] = lo;
}

// ---------------------------------------------------------------------------
// GEMM device helpers
// ---------------------------------------------------------------------------
__device__ __forceinline__ void fill_w_tiles(char* sm, int wl, int tid) {
    const uint4* whi = (const uint4*)g_Wt[wl][0];
    const uint4* wlo = (const uint4*)g_Wt[wl][1];
#pragma unroll
    for (int i = tid; i < 2048; i += 512) {
        int r  = i >> 4;
        int c4 = i & 15;
        uint32_t off = (uint32_t)r * (PADH * 2) + c4 * 16;
        *(uint4*)(sm + 2 * TILEB + off) = __ldg(&whi[i]);
        *(uint4*)(sm + 3 * TILEB + off) = __ldg(&wlo[i]);
    }
}

__device__ __forceinline__ void store_a_split(char* sm, int r, int c4, float4 v) {
    __nv_bfloat16 h0 = __float2bfloat16(v.x), h1 = __float2bfloat16(v.y);
    __nv_bfloat16 h2 = __float2bfloat16(v.z), h3 = __float2bfloat16(v.w);
    __nv_bfloat16 l0 = __float2bfloat16(v.x - __bfloat162float(h0));
    __nv_bfloat16 l1 = __float2bfloat16(v.y - __bfloat162float(h1));
    __nv_bfloat16 l2 = __float2bfloat16(v.z - __bfloat162float(h2));
    __nv_bfloat16 l3 = __float2bfloat16(v.w - __bfloat162float(h3));
    uint32_t off = (uint32_t)r * (PADH * 2) + c4 * 8;
    *(__nv_bfloat162*)(sm + off)             = __halves2bfloat162(h0, h1);
    *(__nv_bfloat162*)(sm + off + 4)         = __halves2bfloat162(h2, h3);
    *(__nv_bfloat162*)(sm + TILEB + off)     = __halves2bfloat162(l0, l1);
    *(__nv_bfloat162*)(sm + TILEB + off + 4) = __halves2bfloat162(l2, l3);
}

// MMA main loop + dinv-scaled fp16 epilogue
__device__ __forceinline__ void mma_and_store(uint32_t uBase, int wid, int lane,
                                              int bm, const float* dinv,
                                              __half* __restrict__ C16) {
    const uint32_t uAhi = uBase;
    const uint32_t uAlo = uBase + TILEB;
    const uint32_t uWhi = uBase + 2 * TILEB;
    const uint32_t uWlo = uBase + 3 * TILEB;
    const int mt = wid >> 1;
    const int nh = wid & 1;
    const int lr = lane & 15;
    const int lc = lane >> 4;

    float acc[8][4];
#pragma unroll
    for (int j = 0; j < 8; j++)
#pragma unroll
        for (int q = 0; q < 4; q++) acc[j][q] = 0.0f;

#pragma unroll
    for (int ks = 0; ks < 8; ks++) {
        uint32_t aoff = (uint32_t)(mt * 16 + lr) * (PADH * 2) + (ks * 16 + lc * 8) * 2;
        uint32_t aH[4], aL[4];
        LDSM_X4(aH, uAhi + aoff);
        LDSM_X4(aL, uAlo + aoff);

        uint32_t brow = (uint32_t)(ks * 16 + lr) * (PADH * 2);
        uint32_t bH[4][4], bL[4][4];
#pragma unroll
        for (int p = 0; p < 4; p++) {
            uint32_t boff = brow + (nh * 64 + p * 16 + lc * 8) * 2;
            LDSM_X4T(bH[p], uWhi + boff);
            LDSM_X4T(bL[p], uWlo + boff);
        }
#pragma unroll
        for (int p = 0; p < 4; p++) {
            MMA_BF16(acc[2 * p],     aH, bH[p][0], bH[p][1]);
            MMA_BF16(acc[2 * p + 1], aH, bH[p][2], bH[p][3]);
            MMA_BF16(acc[2 * p],     aL, bH[p][0], bH[p][1]);
            MMA_BF16(acc[2 * p + 1], aL, bH[p][2], bH[p][3]);
            MMA_BF16(acc[2 * p],     aH, bL[p][0], bL[p][1]);
            MMA_BF16(acc[2 * p + 1], aH, bL[p][2], bL[p][3]);
        }
    }

    int row0 = bm + mt * 16 + (lane >> 2);
    int row1 = row0 + 8;
    float s0 = (row0 < NNODES) ? __ldg(&dinv[row0]) : 0.f;
    float s1 = (row1 < NNODES) ? __ldg(&dinv[row1]) : 0.f;
    int colb = nh * 64 + (lane & 3) * 2;
    if (row0 < NNODES) {
        __half* o = &C16[(size_t)row0 * 128 + colb];
#pragma unroll
        for (int j = 0; j < 8; j++)
            *(__half2*)(o + j * 8) = __floats2half2_rn(acc[j][0] * s0, acc[j][1] * s0);
    }
    if (row1 < NNODES) {
        __half* o = &C16[(size_t)row1 * 128 + colb];
#pragma unroll
        for (int j = 0; j < 8; j++)
            *(__half2*)(o + j * 8) = __floats2half2_rn(acc[j][2] * s1, acc[j][3] * s1);
    }
}

// ---------------------------------------------------------------------------
// Layer-0 GEMM (fp32 A): h16 = fp16( dinv * (x @ W0) )
// ---------------------------------------------------------------------------
__global__ __launch_bounds__(512, 1)
void gemm_f32(const float* __restrict__ A, int wl,
              const float* __restrict__ dinv, __half* __restrict__ C16) {
    extern __shared__ char sm[];
    const int tid  = threadIdx.x;
    const int wid  = tid >> 5;
    const int lane = tid & 31;
    const int bm   = blockIdx.x * MTILE;
    const uint32_t uBase = smem_u32(sm);

    fill_w_tiles(sm, wl, tid);

#pragma unroll
    for (int idx = tid; idx < MTILE * 32; idx += 512) {
        int r  = idx >> 5;
        int c4 = idx & 31;
        int row = bm + r;
        float4 v = make_float4(0.f, 0.f, 0.f, 0.f);
        if (row < NNODES)
            v = *(const float4*)&A[(size_t)row * 128 + c4 * 4];
        store_a_split(sm, r, c4, v);
    }
    __syncthreads();

    mma_and_store(uBase, wid, lane, bm, dinv, C16);
}

// ---------------------------------------------------------------------------
// Layers 1..2 GEMM (fp16 A, already post-bias+relu): h16 = fp16( dinv*(A@W) )
// ---------------------------------------------------------------------------
__global__ __launch_bounds__(512, 1)
void gemm_f16(const __half* __restrict__ A16, int wl,
              const float* __restrict__ dinv, __half* __restrict__ C16) {
    extern __shared__ char sm[];
    const int tid  = threadIdx.x;
    const int wid  = tid >> 5;
    const int lane = tid & 31;
    const int bm   = blockIdx.x * MTILE;
    const uint32_t uBase = smem_u32(sm);

    fill_w_tiles(sm, wl, tid);

    const uint2* ap = (const uint2*)A16;
#pragma unroll
    for (int idx = tid; idx < MTILE * 32; idx += 512) {
        int r  = idx >> 5;
        int c4 = idx & 31;
        int row = bm + r;
        float4 v = make_float4(0.f, 0.f, 0.f, 0.f);
        if (row < NNODES) {
            uint2 u = __ldg(&ap[(size_t)row * 32 + c4]);
            float2 a = __half22float2(*(const __half2*)&u.x);
            float2 b = __half22float2(*(const __half2*)&u.y);
            v = make_float4(a.x, a.y, b.x, b.y);
        }
        store_a_split(sm, r, c4, v);
    }
    __syncthreads();

    mma_and_store(uBase, wid, lane, bm, dinv, C16);
}

// ---------------------------------------------------------------------------
// Mid gather: out16[d,:] = fp16( relu( dinv[d]*(h16[d]+Σ h16[src]) + bias ) )
// One warp per node; lane owns 4 halves.
// ---------------------------------------------------------------------------
__global__ __launch_bounds__(256)
void gather_mid(const __half* __restrict__ hs, const float* __restrict__ bias,
                __half* __restrict__ out16) {
    int w = (int)((blockIdx.x * (unsigned)blockDim.x + threadIdx.x) >> 5);
    if (w >= NNODES) return;
    int lane = threadIdx.x & 31;
    const uint2* hp = (const uint2*)hs;

    int e    = g_off[w];
    int eend = g_off[w + 1];

    float4 acc;
    {
        uint2 u = __ldg(&hp[w * 32 + lane]);
        float2 a = __half22float2(*(const __half2*)&u.x);
        float2 b = __half22float2(*(const __half2*)&u.y);
        acc = make_float4(a.x, a.y, b.x, b.y);
    }

#define ACC_U(u) { \
    float2 _a = __half22float2(*(const __half2*)&(u).x); \
    float2 _b = __half22float2(*(const __half2*)&(u).y); \
    acc.x += _a.x; acc.y += _a.y; acc.z += _b.x; acc.w += _b.y; }
    for (; e + 4 <= eend; e += 4) {
        uint2 u0 = __ldg(&hp[__ldg(&g_csr[e + 0]) * 32 + lane]);
        uint2 u1 = __ldg(&hp[__ldg(&g_csr[e + 1]) * 32 + lane]);
        uint2 u2 = __ldg(&hp[__ldg(&g_csr[e + 2]) * 32 + lane]);
        uint2 u3 = __ldg(&hp[__ldg(&g_csr[e + 3]) * 32 + lane]);
        ACC_U(u0) ACC_U(u1) ACC_U(u2) ACC_U(u3)
    }
    for (; e < eend; e++) {
        uint2 u = __ldg(&hp[__ldg(&g_csr[e]) * 32 + lane]);
        ACC_U(u)
    }

    float sc = __ldg(&g_dinv[w]);
    float4 bb = *(const float4*)&bias[lane * 4];
    acc.x = fmaxf(acc.x * sc + bb.x, 0.f);
    acc.y = fmaxf(acc.y * sc + bb.y, 0.f);
    acc.z = fmaxf(acc.z * sc + bb.z, 0.f);
    acc.w = fmaxf(acc.w * sc + bb.w, 0.f);

    __half2 o0 = __floats2half2_rn(acc.x, acc.y);
    __half2 o1 = __floats2half2_rn(acc.z, acc.w);
    uint2 ou;
    ou.x = *(const uint32_t*)&o0;
    ou.y = *(const uint32_t*)&o1;
    ((uint2*)out16)[w * 32 + lane] = ou;
}

// ---------------------------------------------------------------------------
// Final gather: out = relu( dinv[d]*(h16[d]+Σ h16[src]) + b2 ), fp32.
// ---------------------------------------------------------------------------
__global__ __launch_bounds__(256)
void gather_final(const __half* __restrict__ hs, const float* __restrict__ bias,
                  float* __restrict__ out) {
    int w = (int)((blockIdx.x * (unsigned)blockDim.x + threadIdx.x) >> 5);
    if (w >= NNODES) return;
    int lane = threadIdx.x & 31;
    const uint2* hp = (const uint2*)hs;

    int e    = g_off[w];
    int eend = g_off[w + 1];

    float4 acc;
    {
        uint2 u = __ldg(&hp[w * 32 + lane]);
        float2 a = __half22float2(*(const __half2*)&u.x);
        float2 b = __half22float2(*(const __half2*)&u.y);
        acc = make_float4(a.x, a.y, b.x, b.y);
    }

    for (; e + 4 <= eend; e += 4) {
        uint2 u0 = __ldg(&hp[__ldg(&g_csr[e + 0]) * 32 + lane]);
        uint2 u1 = __ldg(&hp[__ldg(&g_csr[e + 1]) * 32 + lane]);
        uint2 u2 = __ldg(&hp[__ldg(&g_csr[e + 2]) * 32 + lane]);
        uint2 u3 = __ldg(&hp[__ldg(&g_csr[e + 3]) * 32 + lane]);
        ACC_U(u0) ACC_U(u1) ACC_U(u2) ACC_U(u3)
    }
    for (; e < eend; e++) {
        uint2 u = __ldg(&hp[__ldg(&g_csr[e]) * 32 + lane]);
        ACC_U(u)
    }
#undef ACC_U

    float sc = __ldg(&g_dinv[w]);
    float4 bb = *(const float4*)&bias[lane * 4];
    acc.x = fmaxf(acc.x * sc + bb.x, 0.f);
    acc.y = fmaxf(acc.y * sc + bb.y, 0.f);
    acc.z = fmaxf(acc.z * sc + bb.z, 0.f);
    acc.w = fmaxf(acc.w * sc + bb.w, 0.f);
    ((float4*)out)[w * 32 + lane] = acc;
}

// ---------------------------------------------------------------------------
extern "C" void kernel_launch(void* const* d_in, const int* in_sizes, int n_in,
                              void* d_out, int out_size) {
    const float* x  = (const float*)d_in[0];
    const int*   ei = (const int*)d_in[1];
    const float* W0 = (const float*)d_in[2];
    const float* b0 = (const float*)d_in[3];
    const float* W1 = (const float*)d_in[4];
    const float* b1 = (const float*)d_in[5];
    const float* W2 = (const float*)d_in[6];
    const float* b2 = (const float*)d_in[7];
    const int* src = ei;
    const int* dst = ei + EEDGES;

    __half *h16a, *h16b;
    float* dinv;
    cudaGetSymbolAddress((void**)&h16a, g_h16a);
    cudaGetSymbolAddress((void**)&h16b, g_h16b);
    cudaGetSymbolAddress((void**)&dinv, g_dinv);

    cudaFuncSetAttribute(gemm_f32, cudaFuncAttributeMaxDynamicSharedMemorySize, SMEM_DYN);
    cudaFuncSetAttribute(gemm_f16, cudaFuncAttributeMaxDynamicSharedMemorySize, SMEM_DYN);

    // Degree + CSR build
    zero_deg<<<(NNODES + 255) / 256, 256>>>();
    deg_count<<<(EEDGES + 255) / 256, 256>>>(dst);
    dinv_kernel<<<(NNODES + 255) / 256, 256>>>();
    scan1<<<NSCAN, SCAN_T>>>();
    scan2<<<1, 32>>>();
    scan3<<<(NNODES + 255) / 256, 256>>>();
    csr_fill<<<(EEDGES + 255) / 256, 256>>>(src, dst);
    prep_w<<<(3 * 16384 + 255) / 256, 256>>>(W0, W1, W2);

    const int gather_blocks = (NNODES + 7) / 8;

    gemm_f32<<<NTILES, 512, SMEM_DYN>>>(x, 0, dinv, h16a);
    gather_mid<<<gather_blocks, 256>>>(h16a, b0, h16b);
    gemm_f16<<<NTILES, 512, SMEM_DYN>>>(h16b, 1, dinv, h16a);
    gather_mid<<<gather_blocks, 256>>>(h16a, b1, h16b);
    gemm_f16<<<NTILES, 512, SMEM_DYN>>>(h16b, 2, dinv, h16a);
    gather_final<<<gather_blocks, 256>>>(h16a, b2, (float*)d_out);
}

// round 8
// speedup vs baseline: 1.9280x; 1.0874x over previous
#include <cuda_runtime.h>
#include <cuda_fp16.h>
#include <cstdint>

#define NNODES 100000
#define EEDGES 1600000
#define HDIM   128

#define SCAN_BLK 1024
#define SCAN_T   256
#define NSCAN    ((NNODES + SCAN_BLK - 1) / SCAN_BLK)   // 98

#define MTILE   128
#define NTILES  ((NNODES + MTILE - 1) / MTILE)          // 782
#define PADH    136                                      // halves per padded row (272 B)
#define TILEB   (128 * PADH * 2)                         // 34816 B per fp16 tile
#define SMEM_L0 (4 * TILEB)                              // A_hi, A_lo, W_hi, W_lo
#define SMEM_F16 (3 * TILEB)                             // A, W_hi, W_lo

// ---------------------------------------------------------------------------
// Scratch (device globals)
// ---------------------------------------------------------------------------
__device__ __half g_h16a[(size_t)NNODES * HDIM];  // 25.6 MB ping
__device__ __half g_h16b[(size_t)NNODES * HDIM];  // 25.6 MB pong
__device__ float  g_dinv[NNODES];
__device__ int    g_deg[NNODES];
__device__ int    g_off[NNODES + 1];
__device__ int    g_cur[NNODES];
__device__ int    g_csr[EEDGES];
__device__ int    g_bsum[NSCAN];
__device__ int    g_bbase[NSCAN];
__device__ __half g_Wt[3][2][128 * 128];          // k-major W, fp16 hi/lo split

// ---------------------------------------------------------------------------
__device__ __forceinline__ uint32_t smem_u32(const void* p) {
    uint32_t a;
    asm("{ .reg .u64 t; cvta.to.shared.u64 t, %1; cvt.u32.u64 %0, t; }"
        : "=r"(a) : "l"(p));
    return a;
}

#define LDSM_X4(r, a) \
    asm volatile("ldmatrix.sync.aligned.m8n8.x4.shared.b16 {%0,%1,%2,%3}, [%4];" \
                 : "=r"((r)[0]), "=r"((r)[1]), "=r"((r)[2]), "=r"((r)[3]) : "r"(a))
#define LDSM_X4T(r, a) \
    asm volatile("ldmatrix.sync.aligned.m8n8.x4.trans.shared.b16 {%0,%1,%2,%3}, [%4];" \
                 : "=r"((r)[0]), "=r"((r)[1]), "=r"((r)[2]), "=r"((r)[3]) : "r"(a))
#define MMA_F16(c, a, b0, b1) \
    asm volatile("mma.sync.aligned.m16n8k16.row.col.f32.f16.f16.f32 " \
                 "{%0,%1,%2,%3}, {%4,%5,%6,%7}, {%8,%9}, {%0,%1,%2,%3};" \
                 : "+f"((c)[0]), "+f"((c)[1]), "+f"((c)[2]), "+f"((c)[3]) \
                 : "r"((a)[0]), "r"((a)[1]), "r"((a)[2]), "r"((a)[3]), \
                   "r"(b0), "r"(b1))

// ---------------------------------------------------------------------------
// Degree / CSR build
// ---------------------------------------------------------------------------
__global__ void zero_deg() {
    int i = blockIdx.x * blockDim.x + threadIdx.x;
    if (i < NNODES) g_deg[i] = 0;
}
__global__ void deg_count(const int* __restrict__ dst) {
    int e = blockIdx.x * blockDim.x + threadIdx.x;
    if (e < EEDGES) atomicAdd(&g_deg[dst[e]], 1);
}
// scan1 also computes dinv = rsqrt(deg+1)
__global__ __launch_bounds__(SCAN_T)
void scan1() {
    __shared__ int sh[SCAN_T];
    int b = blockIdx.x, t = threadIdx.x;
    int base = b * SCAN_BLK + t * 4;
    int v[4];
#pragma unroll
    for (int j = 0; j < 4; j++) {
        int i = base + j;
        v[j] = (i < NNODES) ? g_deg[i] : 0;
        if (i < NNODES) g_dinv[i] = rsqrtf((float)v[j] + 1.0f);
    }
    int tot = v[0] + v[1] + v[2] + v[3];
    sh[t] = tot;
    __syncthreads();
    for (int o = 1; o < SCAN_T; o <<= 1) {
        int x = 0;
        if (t >= o) x = sh[t - o];
        __syncthreads();
        if (t >= o) sh[t] += x;
        __syncthreads();
    }
    int run = sh[t] - tot;
#pragma unroll
    for (int j = 0; j < 4; j++) {
        int i = base + j;
        if (i < NNODES) g_off[i] = run;
        run += v[j];
    }
    if (t == SCAN_T - 1) g_bsum[b] = sh[t];
}
__global__ void scan2() {
    if (threadIdx.x == 0 && blockIdx.x == 0) {
        int run = 0;
        for (int i = 0; i < NSCAN; i++) { g_bbase[i] = run; run += g_bsum[i]; }
        g_off[NNODES] = run;
    }
}
__global__ void scan3() {
    int i = blockIdx.x * blockDim.x + threadIdx.x;
    if (i < NNODES) {
        int v = g_off[i] + g_bbase[i / SCAN_BLK];
        g_off[i] = v;
        g_cur[i] = v;
    }
}
__global__ void csr_fill(const int* __restrict__ src, const int* __restrict__ dst) {
    int e = blockIdx.x * blockDim.x + threadIdx.x;
    if (e < EEDGES) {
        int d = dst[e];
        int slot = atomicAdd(&g_cur[d], 1);
        g_csr[slot] = src[e];
    }
}

// ---------------------------------------------------------------------------
// Prep: split W (k-major, [k][n]) into fp16 hi/lo (near-exact sum).
// ---------------------------------------------------------------------------
__global__ void prep_w(const float* __restrict__ W0, const float* __restrict__ W1,
                       const float* __restrict__ W2) {
    int idx = blockIdx.x * blockDim.x + threadIdx.x;
    if (idx >= 3 * 16384) return;
    int l = idx >> 14;
    int e = idx & 16383;
    const float* W = (l == 0) ? W0 : (l == 1) ? W1 : W2;
    float v = W[e];
    __half hi = __float2half_rn(v);
    __half lo = __float2half_rn(v - __half2float(hi));
    g_Wt[l][0][e] = hi;
    g_Wt[l][1][e] = lo;
}

// ---------------------------------------------------------------------------
// GEMM device helpers
// ---------------------------------------------------------------------------
// Copy W hi/lo tiles into smem at byte offsets woff, woff+TILEB.
__device__ __forceinline__ void fill_w_tiles(char* sm, uint32_t woff, int wl,
                                             int tid) {
    const uint4* whi = (const uint4*)g_Wt[wl][0];
    const uint4* wlo = (const uint4*)g_Wt[wl][1];
#pragma unroll
    for (int i = tid; i < 2048; i += 512) {
        int r  = i >> 4;
        int c4 = i & 15;
        uint32_t off = (uint32_t)r * (PADH * 2) + c4 * 16;
        *(uint4*)(sm + woff + off)         = __ldg(&whi[i]);
        *(uint4*)(sm + woff + TILEB + off) = __ldg(&wlo[i]);
    }
}

// MMA core: A single tile at uA; B hi/lo at uWhi/uWlo. If DUAL_A, second A
// tile (lo) at uA+TILEB contributes Alo*Whi.
template <bool DUAL_A>
__device__ __forceinline__ void mma_and_store(uint32_t uA, uint32_t uWhi,
                                              int wid, int lane, int bm,
                                              const float* dinv,
                                              __half* __restrict__ C16) {
    const uint32_t uWlo = uWhi + TILEB;
    const int mt = wid >> 1;
    const int nh = wid & 1;
    const int lr = lane & 15;
    const int lc = lane >> 4;

    float acc[8][4];
#pragma unroll
    for (int j = 0; j < 8; j++)
#pragma unroll
        for (int q = 0; q < 4; q++) acc[j][q] = 0.0f;

#pragma unroll
    for (int ks = 0; ks < 8; ks++) {
        uint32_t aoff = (uint32_t)(mt * 16 + lr) * (PADH * 2) + (ks * 16 + lc * 8) * 2;
        uint32_t aH[4], aL[4];
        LDSM_X4(aH, uA + aoff);
        if (DUAL_A) LDSM_X4(aL, uA + TILEB + aoff);

        uint32_t brow = (uint32_t)(ks * 16 + lr) * (PADH * 2);
#pragma unroll
        for (int p = 0; p < 4; p++) {
            uint32_t boff = brow + (nh * 64 + p * 16 + lc * 8) * 2;
            uint32_t bH[4], bL[4];
            LDSM_X4T(bH, uWhi + boff);
            LDSM_X4T(bL, uWlo + boff);
            MMA_F16(acc[2 * p],     aH, bH[0], bH[1]);
            MMA_F16(acc[2 * p + 1], aH, bH[2], bH[3]);
            MMA_F16(acc[2 * p],     aH, bL[0], bL[1]);
            MMA_F16(acc[2 * p + 1], aH, bL[2], bL[3]);
            if (DUAL_A) {
                MMA_F16(acc[2 * p],     aL, bH[0], bH[1]);
                MMA_F16(acc[2 * p + 1], aL, bH[2], bH[3]);
            }
        }
    }

    int row0 = bm + mt * 16 + (lane >> 2);
    int row1 = row0 + 8;
    float s0 = (row0 < NNODES) ? __ldg(&dinv[row0]) : 0.f;
    float s1 = (row1 < NNODES) ? __ldg(&dinv[row1]) : 0.f;
    int colb = nh * 64 + (lane & 3) * 2;
    if (row0 < NNODES) {
        __half* o = &C16[(size_t)row0 * 128 + colb];
#pragma unroll
        for (int j = 0; j < 8; j++)
            *(__half2*)(o + j * 8) = __floats2half2_rn(acc[j][0] * s0, acc[j][1] * s0);
    }
    if (row1 < NNODES) {
        __half* o = &C16[(size_t)row1 * 128 + colb];
#pragma unroll
        for (int j = 0; j < 8; j++)
            *(__half2*)(o + j * 8) = __floats2half2_rn(acc[j][2] * s1, acc[j][3] * s1);
    }
}

// ---------------------------------------------------------------------------
// Layer-0 GEMM (fp32 A, fp16 hi/lo split): h16 = fp16( dinv * (x @ W0) )
// SMEM: A_hi, A_lo, W_hi, W_lo (4 tiles, 1 CTA/SM).
// ---------------------------------------------------------------------------
__global__ __launch_bounds__(512, 1)
void gemm_f32(const float* __restrict__ A,
              const float* __restrict__ dinv, __half* __restrict__ C16) {
    extern __shared__ char sm[];
    const int tid  = threadIdx.x;
    const int wid  = tid >> 5;
    const int lane = tid & 31;
    const int bm   = blockIdx.x * MTILE;
    const uint32_t uBase = smem_u32(sm);

    fill_w_tiles(sm, 2 * TILEB, 0, tid);

#pragma unroll
    for (int idx = tid; idx < MTILE * 32; idx += 512) {
        int r  = idx >> 5;
        int c4 = idx & 31;
        int row = bm + r;
        float4 v = make_float4(0.f, 0.f, 0.f, 0.f);
        if (row < NNODES)
            v = *(const float4*)&A[(size_t)row * 128 + c4 * 4];
        __half h0 = __float2half_rn(v.x), h1 = __float2half_rn(v.y);
        __half h2 = __float2half_rn(v.z), h3 = __float2half_rn(v.w);
        __half l0 = __float2half_rn(v.x - __half2float(h0));
        __half l1 = __float2half_rn(v.y - __half2float(h1));
        __half l2 = __float2half_rn(v.z - __half2float(h2));
        __half l3 = __float2half_rn(v.w - __half2float(h3));
        uint32_t off = (uint32_t)r * (PADH * 2) + c4 * 8;
        *(__half2*)(sm + off)             = __halves2half2(h0, h1);
        *(__half2*)(sm + off + 4)         = __halves2half2(h2, h3);
        *(__half2*)(sm + TILEB + off)     = __halves2half2(l0, l1);
        *(__half2*)(sm + TILEB + off + 4) = __halves2half2(l2, l3);
    }
    __syncthreads();

    mma_and_store<true>(uBase, uBase + 2 * TILEB, wid, lane, bm, dinv, C16);
}

// ---------------------------------------------------------------------------
// Layers 1..2 GEMM (fp16 A, exact): h16 = fp16( dinv*(A@W) )
// SMEM: A, W_hi, W_lo (3 tiles, 2 CTAs/SM).
// ---------------------------------------------------------------------------
__global__ __launch_bounds__(512, 2)
void gemm_f16(const __half* __restrict__ A16, int wl,
              const float* __restrict__ dinv, __half* __restrict__ C16) {
    extern __shared__ char sm[];
    const int tid  = threadIdx.x;
    const int wid  = tid >> 5;
    const int lane = tid & 31;
    const int bm   = blockIdx.x * MTILE;
    const uint32_t uBase = smem_u32(sm);

    fill_w_tiles(sm, TILEB, wl, tid);

    const uint2* ap = (const uint2*)A16;
#pragma unroll
    for (int idx = tid; idx < MTILE * 32; idx += 512) {
        int r  = idx >> 5;
        int c4 = idx & 31;
        int row = bm + r;
        uint2 u = make_uint2(0u, 0u);
        if (row < NNODES) u = __ldg(&ap[(size_t)row * 32 + c4]);
        uint32_t off = (uint32_t)r * (PADH * 2) + c4 * 8;
        *(uint2*)(sm + off) = u;
    }
    __syncthreads();

    mma_and_store<false>(uBase, uBase + TILEB, wid, lane, bm, dinv, C16);
}

// ---------------------------------------------------------------------------
// Mid gather: out16[d,:] = fp16( relu( dinv[d]*(h16[d]+Σ h16[src]) + bias ) )
// One warp per node; lane owns 4 halves; 8-deep unroll for MLP.
// ---------------------------------------------------------------------------
#define ACC_U(u) { \
    float2 _a = __half22float2(*(const __half2*)&(u).x); \
    float2 _b = __half22float2(*(const __half2*)&(u).y); \
    acc.x += _a.x; acc.y += _a.y; acc.z += _b.x; acc.w += _b.y; }

__global__ __launch_bounds__(256)
void gather_mid(const __half* __restrict__ hs, const float* __restrict__ bias,
                __half* __restrict__ out16) {
    int w = (int)((blockIdx.x * (unsigned)blockDim.x + threadIdx.x) >> 5);
    if (w >= NNODES) return;
    int lane = threadIdx.x & 31;
    const uint2* hp = (const uint2*)hs;

    int e    = g_off[w];
    int eend = g_off[w + 1];

    float4 acc = make_float4(0.f, 0.f, 0.f, 0.f);
    {
        uint2 u = __ldg(&hp[w * 32 + lane]);
        ACC_U(u)
    }

    for (; e + 8 <= eend; e += 8) {
        uint2 u0 = __ldg(&hp[__ldg(&g_csr[e + 0]) * 32 + lane]);
        uint2 u1 = __ldg(&hp[__ldg(&g_csr[e + 1]) * 32 + lane]);
        uint2 u2 = __ldg(&hp[__ldg(&g_csr[e + 2]) * 32 + lane]);
        uint2 u3 = __ldg(&hp[__ldg(&g_csr[e + 3]) * 32 + lane]);
        uint2 u4 = __ldg(&hp[__ldg(&g_csr[e + 4]) * 32 + lane]);
        uint2 u5 = __ldg(&hp[__ldg(&g_csr[e + 5]) * 32 + lane]);
        uint2 u6 = __ldg(&hp[__ldg(&g_csr[e + 6]) * 32 + lane]);
        uint2 u7 = __ldg(&hp[__ldg(&g_csr[e + 7]) * 32 + lane]);
        ACC_U(u0) ACC_U(u1) ACC_U(u2) ACC_U(u3)
        ACC_U(u4) ACC_U(u5) ACC_U(u6) ACC_U(u7)
    }
    for (; e < eend; e++) {
        uint2 u = __ldg(&hp[__ldg(&g_csr[e]) * 32 + lane]);
        ACC_U(u)
    }

    float sc = __ldg(&g_dinv[w]);
    float4 bb = *(const float4*)&bias[lane * 4];
    acc.x = fmaxf(acc.x * sc + bb.x, 0.f);
    acc.y = fmaxf(acc.y * sc + bb.y, 0.f);
    acc.z = fmaxf(acc.z * sc + bb.z, 0.f);
    acc.w = fmaxf(acc.w * sc + bb.w, 0.f);

    __half2 o0 = __floats2half2_rn(acc.x, acc.y);
    __half2 o1 = __floats2half2_rn(acc.z, acc.w);
    uint2 ou;
    ou.x = *(const uint32_t*)&o0;
    ou.y = *(const uint32_t*)&o1;
    ((uint2*)out16)[w * 32 + lane] = ou;
}

// ---------------------------------------------------------------------------
// Final gather: out = relu( dinv[d]*(h16[d]+Σ h16[src]) + b2 ), fp32.
// ---------------------------------------------------------------------------
__global__ __launch_bounds__(256)
void gather_final(const __half* __restrict__ hs, const float* __restrict__ bias,
                  float* __restrict__ out) {
    int w = (int)((blockIdx.x * (unsigned)blockDim.x + threadIdx.x) >> 5);
    if (w >= NNODES) return;
    int lane = threadIdx.x & 31;
    const uint2* hp = (const uint2*)hs;

    int e    = g_off[w];
    int eend = g_off[w + 1];

    float4 acc = make_float4(0.f, 0.f, 0.f, 0.f);
    {
        uint2 u = __ldg(&hp[w * 32 + lane]);
        ACC_U(u)
    }

    for (; e + 8 <= eend; e += 8) {
        uint2 u0 = __ldg(&hp[__ldg(&g_csr[e + 0]) * 32 + lane]);
        uint2 u1 = __ldg(&hp[__ldg(&g_csr[e + 1]) * 32 + lane]);
        uint2 u2 = __ldg(&hp[__ldg(&g_csr[e + 2]) * 32 + lane]);
        uint2 u3 = __ldg(&hp[__ldg(&g_csr[e + 3]) * 32 + lane]);
        uint2 u4 = __ldg(&hp[__ldg(&g_csr[e + 4]) * 32 + lane]);
        uint2 u5 = __ldg(&hp[__ldg(&g_csr[e + 5]) * 32 + lane]);
        uint2 u6 = __ldg(&hp[__ldg(&g_csr[e + 6]) * 32 + lane]);
        uint2 u7 = __ldg(&hp[__ldg(&g_csr[e + 7]) * 32 + lane]);
        ACC_U(u0) ACC_U(u1) ACC_U(u2) ACC_U(u3)
        ACC_U(u4) ACC_U(u5) ACC_U(u6) ACC_U(u7)
    }
    for (; e < eend; e++) {
        uint2 u = __ldg(&hp[__ldg(&g_csr[e]) * 32 + lane]);
        ACC_U(u)
    }

    float sc = __ldg(&g_dinv[w]);
    float4 bb = *(const float4*)&bias[lane * 4];
    acc.x = fmaxf(acc.x * sc + bb.x, 0.f);
    acc.y = fmaxf(acc.y * sc + bb.y, 0.f);
    acc.z = fmaxf(acc.z * sc + bb.z, 0.f);
    acc.w = fmaxf(acc.w * sc + bb.w, 0.f);
    ((float4*)out)[w * 32 + lane] = acc;
}
#undef ACC_U

// ---------------------------------------------------------------------------
extern "C" void kernel_launch(void* const* d_in, const int* in_sizes, int n_in,
                              void* d_out, int out_size) {
    const float* x  = (const float*)d_in[0];
    const int*   ei = (const int*)d_in[1];
    const float* W0 = (const float*)d_in[2];
    const float* b0 = (const float*)d_in[3];
    const float* W1 = (const float*)d_in[4];
    const float* b1 = (const float*)d_in[5];
    const float* W2 = (const float*)d_in[6];
    const float* b2 = (const float*)d_in[7];
    const int* src = ei;
    const int* dst = ei + EEDGES;

    __half *h16a, *h16b;
    float* dinv;
    cudaGetSymbolAddress((void**)&h16a, g_h16a);
    cudaGetSymbolAddress((void**)&h16b, g_h16b);
    cudaGetSymbolAddress((void**)&dinv, g_dinv);

    cudaFuncSetAttribute(gemm_f32, cudaFuncAttributeMaxDynamicSharedMemorySize, SMEM_L0);
    cudaFuncSetAttribute(gemm_f16, cudaFuncAttributeMaxDynamicSharedMemorySize, SMEM_F16);

    // Degree + CSR build
    zero_deg<<<(NNODES + 255) / 256, 256>>>();
    deg_count<<<(EEDGES + 255) / 256, 256>>>(dst);
    scan1<<<NSCAN, SCAN_T>>>();
    scan2<<<1, 32>>>();
    scan3<<<(NNODES + 255) / 256, 256>>>();
    csr_fill<<<(EEDGES + 255) / 256, 256>>>(src, dst);
    prep_w<<<(3 * 16384 + 255) / 256, 256>>>(W0, W1, W2);

    const int gather_blocks = (NNODES + 7) / 8;

    gemm_f32<<<NTILES, 512, SMEM_L0>>>(x, dinv, h16a);
    gather_mid<<<gather_blocks, 256>>>(h16a, b0, h16b);
    gemm_f16<<<NTILES, 512, SMEM_F16>>>(h16b, 1, dinv, h16a);
    gather_mid<<<gather_blocks, 256>>>(h16a, b1, h16b);
    gemm_f16<<<NTILES, 512, SMEM_F16>>>(h16b, 2, dinv, h16a);
    gather_final<<<gather_blocks, 256>>>(h16a, b2, (float*)d_out);
}

// round 9
// speedup vs baseline: 1.9601x; 1.0166x over previous
#include <cuda_runtime.h>
#include <cuda_fp16.h>
#include <cstdint>

#define NNODES 100000
#define EEDGES 1600000
#define HDIM   128

#define SCAN_BLK 1024
#define SCAN_T   256
#define NSCAN    ((NNODES + SCAN_BLK - 1) / SCAN_BLK)   // 98

#define MTILE   128
#define NTILES  ((NNODES + MTILE - 1) / MTILE)          // 782
#define PADH    136                                      // halves per padded row (272 B)
#define TILEB   (128 * PADH * 2)                         // 34816 B per fp16 tile
#define SMEM_L0 (4 * TILEB)                              // A_hi, A_lo, W_hi, W_lo
#define SMEM_F16 (3 * TILEB)                             // A, W_hi, W_lo

// ---------------------------------------------------------------------------
// Scratch (device globals)
// ---------------------------------------------------------------------------
__device__ __half g_h16a[(size_t)NNODES * HDIM];  // 25.6 MB ping
__device__ __half g_h16b[(size_t)NNODES * HDIM];  // 25.6 MB pong
__device__ float  g_dinv[NNODES];
__device__ int    g_deg[NNODES];
__device__ int    g_off[NNODES + 1];
__device__ int    g_cur[NNODES];
__device__ int    g_csr[EEDGES];
__device__ int    g_bsum[NSCAN];
__device__ int    g_bbase[NSCAN];
__device__ __half g_Wt[3][2][128 * 128];          // k-major W, fp16 hi/lo split

// ---------------------------------------------------------------------------
__device__ __forceinline__ uint32_t smem_u32(const void* p) {
    uint32_t a;
    asm("{ .reg .u64 t; cvta.to.shared.u64 t, %1; cvt.u32.u64 %0, t; }"
        : "=r"(a) : "l"(p));
    return a;
}

#define LDSM_X4(r, a) \
    asm volatile("ldmatrix.sync.aligned.m8n8.x4.shared.b16 {%0,%1,%2,%3}, [%4];" \
                 : "=r"((r)[0]), "=r"((r)[1]), "=r"((r)[2]), "=r"((r)[3]) : "r"(a))
#define LDSM_X4T(r, a) \
    asm volatile("ldmatrix.sync.aligned.m8n8.x4.trans.shared.b16 {%0,%1,%2,%3}, [%4];" \
                 : "=r"((r)[0]), "=r"((r)[1]), "=r"((r)[2]), "=r"((r)[3]) : "r"(a))
#define MMA_F16(c, a, b0, b1) \
    asm volatile("mma.sync.aligned.m16n8k16.row.col.f32.f16.f16.f32 " \
                 "{%0,%1,%2,%3}, {%4,%5,%6,%7}, {%8,%9}, {%0,%1,%2,%3};" \
                 : "+f"((c)[0]), "+f"((c)[1]), "+f"((c)[2]), "+f"((c)[3]) \
                 : "r"((a)[0]), "r"((a)[1]), "r"((a)[2]), "r"((a)[3]), \
                   "r"(b0), "r"(b1))

// ---------------------------------------------------------------------------
// Degree / CSR build
// ---------------------------------------------------------------------------
__global__ void deg_count(const int* __restrict__ dst) {
    int e = blockIdx.x * blockDim.x + threadIdx.x;
    if (e < EEDGES) atomicAdd(&g_deg[dst[e]], 1);
}
// scan1 also computes dinv = rsqrt(deg+1)
__global__ __launch_bounds__(SCAN_T)
void scan1() {
    __shared__ int sh[SCAN_T];
    int b = blockIdx.x, t = threadIdx.x;
    int base = b * SCAN_BLK + t * 4;
    int v[4];
#pragma unroll
    for (int j = 0; j < 4; j++) {
        int i = base + j;
        v[j] = (i < NNODES) ? g_deg[i] : 0;
        if (i < NNODES) g_dinv[i] = rsqrtf((float)v[j] + 1.0f);
    }
    int tot = v[0] + v[1] + v[2] + v[3];
    sh[t] = tot;
    __syncthreads();
    for (int o = 1; o < SCAN_T; o <<= 1) {
        int x = 0;
        if (t >= o) x = sh[t - o];
        __syncthreads();
        sh[t] += x;
        __syncthreads();
    }
    int run = sh[t] - tot;
#pragma unroll
    for (int j = 0; j < 4; j++) {
        int i = base + j;
        if (i < NNODES) g_off[i] = run;
        run += v[j];
    }
    if (t == SCAN_T - 1) g_bsum[b] = sh[t];
}
// parallel scan of the 98 block sums (one 128-thread block)
__global__ void scan2p() {
    __shared__ int sh[128];
    int t = threadIdx.x;
    int v = (t < NSCAN) ? g_bsum[t] : 0;
    sh[t] = v;
    __syncthreads();
    for (int o = 1; o < 128; o <<= 1) {
        int x = 0;
        if (t >= o) x = sh[t - o];
        __syncthreads();
        sh[t] += x;
        __syncthreads();
    }
    if (t < NSCAN) g_bbase[t] = sh[t] - v;
    if (t == 127) g_off[NNODES] = sh[127];
}
__global__ void scan3() {
    int i = blockIdx.x * blockDim.x + threadIdx.x;
    if (i < NNODES) {
        int v = g_off[i] + g_bbase[i / SCAN_BLK];
        g_off[i] = v;
        g_cur[i] = v;
    }
}
__global__ void csr_fill(const int* __restrict__ src, const int* __restrict__ dst) {
    int e = blockIdx.x * blockDim.x + threadIdx.x;
    if (e < EEDGES) {
        int d = dst[e];
        int slot = atomicAdd(&g_cur[d], 1);
        g_csr[slot] = src[e];
    }
}

// ---------------------------------------------------------------------------
// Prep: split W (k-major, [k][n]) into fp16 hi/lo (near-exact sum).
// ---------------------------------------------------------------------------
__global__ void prep_w(const float* __restrict__ W0, const float* __restrict__ W1,
                       const float* __restrict__ W2) {
    int idx = blockIdx.x * blockDim.x + threadIdx.x;
    if (idx >= 3 * 16384) return;
    int l = idx >> 14;
    int e = idx & 16383;
    const float* W = (l == 0) ? W0 : (l == 1) ? W1 : W2;
    float v = W[e];
    __half hi = __float2half_rn(v);
    __half lo = __float2half_rn(v - __half2float(hi));
    g_Wt[l][0][e] = hi;
    g_Wt[l][1][e] = lo;
}

// ---------------------------------------------------------------------------
// GEMM device helpers
// ---------------------------------------------------------------------------
__device__ __forceinline__ void fill_w_tiles(char* sm, uint32_t woff, int wl,
                                             int tid) {
    const uint4* whi = (const uint4*)g_Wt[wl][0];
    const uint4* wlo = (const uint4*)g_Wt[wl][1];
#pragma unroll
    for (int i = tid; i < 2048; i += 512) {
        int r  = i >> 4;
        int c4 = i & 15;
        uint32_t off = (uint32_t)r * (PADH * 2) + c4 * 16;
        *(uint4*)(sm + woff + off)         = __ldg(&whi[i]);
        *(uint4*)(sm + woff + TILEB + off) = __ldg(&wlo[i]);
    }
}

// MMA core. If DUAL_A, second A tile (lo) at uA+TILEB adds Alo*Whi.
// If SCALE, multiply rows by dinv[row] before fp16 store.
template <bool DUAL_A, bool SCALE>
__device__ __forceinline__ void mma_and_store(uint32_t uA, uint32_t uWhi,
                                              int wid, int lane, int bm,
                                              const float* dinv,
                                              __half* __restrict__ C16) {
    const uint32_t uWlo = uWhi + TILEB;
    const int mt = wid >> 1;
    const int nh = wid & 1;
    const int lr = lane & 15;
    const int lc = lane >> 4;

    float acc[8][4];
#pragma unroll
    for (int j = 0; j < 8; j++)
#pragma unroll
        for (int q = 0; q < 4; q++) acc[j][q] = 0.0f;

#pragma unroll
    for (int ks = 0; ks < 8; ks++) {
        uint32_t aoff = (uint32_t)(mt * 16 + lr) * (PADH * 2) + (ks * 16 + lc * 8) * 2;
        uint32_t aH[4], aL[4];
        LDSM_X4(aH, uA + aoff);
        if (DUAL_A) LDSM_X4(aL, uA + TILEB + aoff);

        uint32_t brow = (uint32_t)(ks * 16 + lr) * (PADH * 2);
#pragma unroll
        for (int p = 0; p < 4; p++) {
            uint32_t boff = brow + (nh * 64 + p * 16 + lc * 8) * 2;
            uint32_t bH[4], bL[4];
            LDSM_X4T(bH, uWhi + boff);
            LDSM_X4T(bL, uWlo + boff);
            MMA_F16(acc[2 * p],     aH, bH[0], bH[1]);
            MMA_F16(acc[2 * p + 1], aH, bH[2], bH[3]);
            MMA_F16(acc[2 * p],     aH, bL[0], bL[1]);
            MMA_F16(acc[2 * p + 1], aH, bL[2], bL[3]);
            if (DUAL_A) {
                MMA_F16(acc[2 * p],     aL, bH[0], bH[1]);
                MMA_F16(acc[2 * p + 1], aL, bH[2], bH[3]);
            }
        }
    }

    int row0 = bm + mt * 16 + (lane >> 2);
    int row1 = row0 + 8;
    float s0 = 1.f, s1 = 1.f;
    if (SCALE) {
        s0 = (row0 < NNODES) ? __ldg(&dinv[row0]) : 0.f;
        s1 = (row1 < NNODES) ? __ldg(&dinv[row1]) : 0.f;
    }
    int colb = nh * 64 + (lane & 3) * 2;
    if (row0 < NNODES) {
        __half* o = &C16[(size_t)row0 * 128 + colb];
#pragma unroll
        for (int j = 0; j < 8; j++)
            *(__half2*)(o + j * 8) = __floats2half2_rn(acc[j][0] * s0, acc[j][1] * s0);
    }
    if (row1 < NNODES) {
        __half* o = &C16[(size_t)row1 * 128 + colb];
#pragma unroll
        for (int j = 0; j < 8; j++)
            *(__half2*)(o + j * 8) = __floats2half2_rn(acc[j][2] * s1, acc[j][3] * s1);
    }
}

// ---------------------------------------------------------------------------
// Layer-0 GEMM (fp32 A, fp16 hi/lo split, NO dinv — applied in gather):
//   h16 = fp16( x @ W0 )
// ---------------------------------------------------------------------------
__global__ __launch_bounds__(512, 1)
void gemm_f32(const float* __restrict__ A, __half* __restrict__ C16) {
    extern __shared__ char sm[];
    const int tid  = threadIdx.x;
    const int wid  = tid >> 5;
    const int lane = tid & 31;
    const int bm   = blockIdx.x * MTILE;
    const uint32_t uBase = smem_u32(sm);

    fill_w_tiles(sm, 2 * TILEB, 0, tid);

#pragma unroll
    for (int idx = tid; idx < MTILE * 32; idx += 512) {
        int r  = idx >> 5;
        int c4 = idx & 31;
        int row = bm + r;
        float4 v = make_float4(0.f, 0.f, 0.f, 0.f);
        if (row < NNODES)
            v = *(const float4*)&A[(size_t)row * 128 + c4 * 4];
        __half h0 = __float2half_rn(v.x), h1 = __float2half_rn(v.y);
        __half h2 = __float2half_rn(v.z), h3 = __float2half_rn(v.w);
        __half l0 = __float2half_rn(v.x - __half2float(h0));
        __half l1 = __float2half_rn(v.y - __half2float(h1));
        __half l2 = __float2half_rn(v.z - __half2float(h2));
        __half l3 = __float2half_rn(v.w - __half2float(h3));
        uint32_t off = (uint32_t)r * (PADH * 2) + c4 * 8;
        *(__half2*)(sm + off)             = __halves2half2(h0, h1);
        *(__half2*)(sm + off + 4)         = __halves2half2(h2, h3);
        *(__half2*)(sm + TILEB + off)     = __halves2half2(l0, l1);
        *(__half2*)(sm + TILEB + off + 4) = __halves2half2(l2, l3);
    }
    __syncthreads();

    mma_and_store<true, false>(uBase, uBase + 2 * TILEB, wid, lane, bm, nullptr, C16);
}

// ---------------------------------------------------------------------------
// Layers 1..2 GEMM (fp16 A, exact): h16 = fp16( dinv*(A@W) )
// ---------------------------------------------------------------------------
__global__ __launch_bounds__(512, 2)
void gemm_f16(const __half* __restrict__ A16, int wl,
              const float* __restrict__ dinv, __half* __restrict__ C16) {
    extern __shared__ char sm[];
    const int tid  = threadIdx.x;
    const int wid  = tid >> 5;
    const int lane = tid & 31;
    const int bm   = blockIdx.x * MTILE;
    const uint32_t uBase = smem_u32(sm);

    fill_w_tiles(sm, TILEB, wl, tid);

    const uint2* ap = (const uint2*)A16;
#pragma unroll
    for (int idx = tid; idx < MTILE * 32; idx += 512) {
        int r  = idx >> 5;
        int c4 = idx & 31;
        int row = bm + r;
        uint2 u = make_uint2(0u, 0u);
        if (row < NNODES) u = __ldg(&ap[(size_t)row * 32 + c4]);
        uint32_t off = (uint32_t)r * (PADH * 2) + c4 * 8;
        *(uint2*)(sm + off) = u;
    }
    __syncthreads();

    mma_and_store<false, true>(uBase, uBase + TILEB, wid, lane, bm, dinv, C16);
}

// ---------------------------------------------------------------------------
// Gather (templated). SRC_SCALED: h already carries dinv[src] (layers 1,2).
// Else (layer 0): weight each message by dinv[s], self by dinv[d].
// FINAL_F32: write fp32 to out; else fp16.
// ---------------------------------------------------------------------------
#define ACCW(u, wgt) { \
    float2 _a = __half22float2(*(const __half2*)&(u).x); \
    float2 _b = __half22float2(*(const __half2*)&(u).y); \
    acc.x += _a.x * (wgt); acc.y += _a.y * (wgt); \
    acc.z += _b.x * (wgt); acc.w += _b.y * (wgt); }

template <bool SRC_SCALED, bool FINAL_F32>
__global__ __launch_bounds__(256)
void gather_k(const __half* __restrict__ hs, const float* __restrict__ bias,
              void* __restrict__ outv) {
    int w = (int)((blockIdx.x * (unsigned)blockDim.x + threadIdx.x) >> 5);
    if (w >= NNODES) return;
    int lane = threadIdx.x & 31;
    const uint2* hp = (const uint2*)hs;

    int e    = g_off[w];
    int eend = g_off[w + 1];
    float sc = __ldg(&g_dinv[w]);

    float4 acc = make_float4(0.f, 0.f, 0.f, 0.f);
    {
        uint2 u = __ldg(&hp[w * 32 + lane]);
        float wgt = SRC_SCALED ? 1.f : sc;
        ACCW(u, wgt)
    }

    for (; e + 8 <= eend; e += 8) {
        int s0 = __ldg(&g_csr[e + 0]);
        int s1 = __ldg(&g_csr[e + 1]);
        int s2 = __ldg(&g_csr[e + 2]);
        int s3 = __ldg(&g_csr[e + 3]);
        int s4 = __ldg(&g_csr[e + 4]);
        int s5 = __ldg(&g_csr[e + 5]);
        int s6 = __ldg(&g_csr[e + 6]);
        int s7 = __ldg(&g_csr[e + 7]);
        uint2 u0 = __ldg(&hp[s0 * 32 + lane]);
        uint2 u1 = __ldg(&hp[s1 * 32 + lane]);
        uint2 u2 = __ldg(&hp[s2 * 32 + lane]);
        uint2 u3 = __ldg(&hp[s3 * 32 + lane]);
        uint2 u4 = __ldg(&hp[s4 * 32 + lane]);
        uint2 u5 = __ldg(&hp[s5 * 32 + lane]);
        uint2 u6 = __ldg(&hp[s6 * 32 + lane]);
        uint2 u7 = __ldg(&hp[s7 * 32 + lane]);
        if (SRC_SCALED) {
            ACCW(u0, 1.f) ACCW(u1, 1.f) ACCW(u2, 1.f) ACCW(u3, 1.f)
            ACCW(u4, 1.f) ACCW(u5, 1.f) ACCW(u6, 1.f) ACCW(u7, 1.f)
        } else {
            ACCW(u0, __ldg(&g_dinv[s0])) ACCW(u1, __ldg(&g_dinv[s1]))
            ACCW(u2, __ldg(&g_dinv[s2])) ACCW(u3, __ldg(&g_dinv[s3]))
            ACCW(u4, __ldg(&g_dinv[s4])) ACCW(u5, __ldg(&g_dinv[s5]))
            ACCW(u6, __ldg(&g_dinv[s6])) ACCW(u7, __ldg(&g_dinv[s7]))
        }
    }
    for (; e < eend; e++) {
        int s = __ldg(&g_csr[e]);
        uint2 u = __ldg(&hp[s * 32 + lane]);
        float wgt = SRC_SCALED ? 1.f : __ldg(&g_dinv[s]);
        ACCW(u, wgt)
    }

    float4 bb = *(const float4*)&bias[lane * 4];
    acc.x = fmaxf(acc.x * sc + bb.x, 0.f);
    acc.y = fmaxf(acc.y * sc + bb.y, 0.f);
    acc.z = fmaxf(acc.z * sc + bb.z, 0.f);
    acc.w = fmaxf(acc.w * sc + bb.w, 0.f);

    if (FINAL_F32) {
        ((float4*)outv)[w * 32 + lane] = acc;
    } else {
        __half2 o0 = __floats2half2_rn(acc.x, acc.y);
        __half2 o1 = __floats2half2_rn(acc.z, acc.w);
        uint2 ou;
        ou.x = *(const uint32_t*)&o0;
        ou.y = *(const uint32_t*)&o1;
        ((uint2*)outv)[w * 32 + lane] = ou;
    }
}
#undef ACCW

// ---------------------------------------------------------------------------
extern "C" void kernel_launch(void* const* d_in, const int* in_sizes, int n_in,
                              void* d_out, int out_size) {
    const float* x  = (const float*)d_in[0];
    const int*   ei = (const int*)d_in[1];
    const float* W0 = (const float*)d_in[2];
    const float* b0 = (const float*)d_in[3];
    const float* W1 = (const float*)d_in[4];
    const float* b1 = (const float*)d_in[5];
    const float* W2 = (const float*)d_in[6];
    const float* b2 = (const float*)d_in[7];
    const int* src = ei;
    const int* dst = ei + EEDGES;

    __half *h16a, *h16b;
    float* dinv;
    int*   deg;
    cudaGetSymbolAddress((void**)&h16a, g_h16a);
    cudaGetSymbolAddress((void**)&h16b, g_h16b);
    cudaGetSymbolAddress((void**)&dinv, g_dinv);
    cudaGetSymbolAddress((void**)&deg,  g_deg);

    cudaFuncSetAttribute(gemm_f32, cudaFuncAttributeMaxDynamicSharedMemorySize, SMEM_L0);
    cudaFuncSetAttribute(gemm_f16, cudaFuncAttributeMaxDynamicSharedMemorySize, SMEM_F16);

    static cudaStream_t s2 = nullptr;
    static cudaEvent_t evFork = nullptr, evJoin = nullptr;
    if (!s2) {
        cudaStreamCreateWithFlags(&s2, cudaStreamNonBlocking);
        cudaEventCreateWithFlags(&evFork, cudaEventDisableTiming);
        cudaEventCreateWithFlags(&evJoin, cudaEventDisableTiming);
    }

    // Fork: side stream does W prep + layer-0 GEMM (independent of CSR chain)
    cudaEventRecord(evFork, 0);
    cudaStreamWaitEvent(s2, evFork, 0);
    prep_w<<<(3 * 16384 + 255) / 256, 256, 0, s2>>>(W0, W1, W2);
    gemm_f32<<<NTILES, 512, SMEM_L0, s2>>>(x, h16a);
    cudaEventRecord(evJoin, s2);

    // Main stream: degree + CSR build
    cudaMemsetAsync(deg, 0, NNODES * sizeof(int), 0);
    deg_count<<<(EEDGES + 255) / 256, 256>>>(dst);
    scan1<<<NSCAN, SCAN_T>>>();
    scan2p<<<1, 128>>>();
    scan3<<<(NNODES + 255) / 256, 256>>>();
    csr_fill<<<(EEDGES + 255) / 256, 256>>>(src, dst);

    // Join, then the serial layer chain
    cudaStreamWaitEvent(0, evJoin, 0);

    const int gather_blocks = (NNODES + 7) / 8;
    gather_k<false, false><<<gather_blocks, 256>>>(h16a, b0, h16b);
    gemm_f16<<<NTILES, 512, SMEM_F16>>>(h16b, 1, dinv, h16a);
    gather_k<true, false><<<gather_blocks, 256>>>(h16a, b1, h16b);
    gemm_f16<<<NTILES, 512, SMEM_F16>>>(h16b, 2, dinv, h16a);
    gather_k<true, true><<<gather_blocks, 256>>>(h16a, b2, d_out);
}